// round 5
// baseline (speedup 1.0000x reference)
#include <cuda_runtime.h>
#include <math.h>

// Problem constants (fixed by the dataset)
#define NE 4096
#define NW 8192
#define KD 128
#define GG 1024
#define MM 64
#define JJ 256

#define NBLK 1184   // 148 SMs * 8 blocks (main kernel)
#define NTHR 256
#define PBLK (KD + GG + 1)   // prep grid: 128 slice blocks + 1024 Sw blocks + 1 entity

// Scratch (device globals — no runtime allocation allowed)
__device__ float g_part[KD * GG]; // per-(k,g) partial distance sums (512 KB)
__device__ float g_swsum[GG];     // per-group sum of gathered Sw values
__device__ float g_pr[NBLK];
__device__ float g_pw[NBLK];
__device__ float g_pe[NBLK];
__device__ float g_sim[GG];
__device__ float g_ent[2];
__device__ int   g_done = 0;      // completion ticket (reset each call)

__device__ __forceinline__ float block_reduce(float v) {
    __shared__ float sh[32];
    int lane = threadIdx.x & 31;
    int wid  = threadIdx.x >> 5;
    #pragma unroll
    for (int o = 16; o > 0; o >>= 1) v += __shfl_down_sync(0xffffffffu, v, o);
    __syncthreads();
    if (lane == 0) sh[wid] = v;
    __syncthreads();
    v = (threadIdx.x < (NTHR >> 5)) ? sh[threadIdx.x] : 0.0f;
    if (wid == 0) {
        #pragma unroll
        for (int o = 16; o > 0; o >>= 1) v += __shfl_down_sync(0xffffffffu, v, o);
    }
    return v;   // valid in thread 0
}

// ---------------------------------------------------------------------------
// K1: prep.
//  blocks [0, KD):      k-slice gather — W row k in smem, all groups' partials
//  blocks [KD, KD+GG):  Sw row-sum for group (b - KD)
//  block  KD+GG:        entity term
// ---------------------------------------------------------------------------
__global__ void __launch_bounds__(NTHR)
prep_k(const float* __restrict__ W,
       const float* __restrict__ E,
       const float* __restrict__ Sw,
       const float* __restrict__ Se,
       const int*   __restrict__ rowi,
       const int*   __restrict__ wi,
       const int*   __restrict__ ej,
       const int*   __restrict__ sj) {
    const int b = blockIdx.x;
    const int t = threadIdx.x;

    __shared__ float row[NW];     // 32 KB

    if (b < KD) {
        // ---- load W row b (coalesced float4) ----
        const float4* w4 = (const float4*)(W + (size_t)b * NW);
        float4* r4 = (float4*)row;
        #pragma unroll 4
        for (int i = t; i < NW / 4; i += NTHR) r4[i] = w4[i];
        __syncthreads();

        // ---- each thread owns groups t, t+256, t+512, t+768 ----
        #pragma unroll
        for (int gg = 0; gg < GG / NTHR; gg++) {
            const int g = t + gg * NTHR;
            const float wj = row[sj[g]];
            const int4* wi4 = (const int4*)(wi + g * MM);
            float acc = 0.0f;
            #pragma unroll
            for (int m4 = 0; m4 < MM / 4; m4++) {
                int4 ii = wi4[m4];
                float d;
                d = wj - row[ii.x]; acc += d * d;
                d = wj - row[ii.y]; acc += d * d;
                d = wj - row[ii.z]; acc += d * d;
                d = wj - row[ii.w]; acc += d * d;
            }
            g_part[b * GG + g] = acc;   // coalesced across t
        }
    } else if (b < KD + GG) {
        const int g = b - KD;
        const int j = sj[g];
        float swv = (t < MM) ? Sw[(size_t)j * NW + wi[g * MM + t]] : 0.0f;
        float sw = block_reduce(swv);
        if (t == 0) g_swsum[g] = sw;
    } else {
        // ---- entity term ----
        __shared__ int ejs[JJ];
        const int row_i = rowi[0];
        if (t < JJ) ejs[t] = ej[t];
        __syncthreads();
        float s_de = 0.0f;
        for (int i = t; i < JJ * KD; i += NTHR) {
            int jj = i >> 7;
            int kk = i & (KD - 1);
            float d = E[(size_t)row_i * KD + kk] - E[(size_t)ejs[jj] * KD + kk];
            s_de += d * d;
        }
        float s_se = (t < JJ) ? Se[(size_t)row_i * NE + ejs[t]] : 0.0f;
        float de = block_reduce(s_de);
        __syncthreads();
        float se = block_reduce(s_se);
        if (t == 0) { g_ent[0] = de; g_ent[1] = se; }
    }
}

// ---------------------------------------------------------------------------
// K2: main — tiny sim finish, HBM streaming reduce, ticket final compose.
// __launch_bounds__(256, 8) pins regs to 32 so the streaming loop keeps
// 8 blocks/SM (occ ~99%) — the R4 lesson.
// ---------------------------------------------------------------------------
__global__ void __launch_bounds__(NTHR, 8)
main_k(const float* __restrict__ actual,
       const float* __restrict__ pred,
       const float* __restrict__ W,
       const float* __restrict__ E,
       const float* __restrict__ lamb,
       float* __restrict__ out) {
    const int b = blockIdx.x;
    const int t = threadIdx.x;
    const int tid    = b * NTHR + t;
    const int stride = NBLK * NTHR;

    // ---- Phase A: finish sim[g] for g = b (128 strided loads + sqrt) ----
    if (b < GG) {
        float acc = (t < KD) ? g_part[t * GG + b] : 0.0f;
        float d2 = block_reduce(acc);
        if (t == 0) g_sim[b] = sqrtf(d2) * g_swsum[b];
    }

    // ---- Phase B: HBM streaming reduce (unchanged from R2) ----
    const float4* a4 = (const float4*)actual;
    const float4* p4 = (const float4*)pred;
    const int n4 = (NE * NW) / 4;     // 8M

    float s0 = 0.f, s1 = 0.f, s2 = 0.f, s3 = 0.f;
    int i = tid;
    for (; i + 3 * stride < n4; i += 4 * stride) {
        float4 av0 = a4[i];
        float4 av1 = a4[i +     stride];
        float4 av2 = a4[i + 2 * stride];
        float4 av3 = a4[i + 3 * stride];
        float4 pv0 = p4[i];
        float4 pv1 = p4[i +     stride];
        float4 pv2 = p4[i + 2 * stride];
        float4 pv3 = p4[i + 3 * stride];
        float d;
        d = av0.x - pv0.x; s0 += d * d; d = av0.y - pv0.y; s0 += d * d;
        d = av0.z - pv0.z; s0 += d * d; d = av0.w - pv0.w; s0 += d * d;
        d = av1.x - pv1.x; s1 += d * d; d = av1.y - pv1.y; s1 += d * d;
        d = av1.z - pv1.z; s1 += d * d; d = av1.w - pv1.w; s1 += d * d;
        d = av2.x - pv2.x; s2 += d * d; d = av2.y - pv2.y; s2 += d * d;
        d = av2.z - pv2.z; s2 += d * d; d = av2.w - pv2.w; s2 += d * d;
        d = av3.x - pv3.x; s3 += d * d; d = av3.y - pv3.y; s3 += d * d;
        d = av3.z - pv3.z; s3 += d * d; d = av3.w - pv3.w; s3 += d * d;
    }
    for (; i < n4; i += stride) {
        float4 av = a4[i];
        float4 pv = p4[i];
        float d;
        d = av.x - pv.x; s0 += d * d; d = av.y - pv.y; s0 += d * d;
        d = av.z - pv.z; s0 += d * d; d = av.w - pv.w; s0 += d * d;
    }
    float s_r = (s0 + s1) + (s2 + s3);

    float s_w = 0.0f;
    {
        const float4* w4 = (const float4*)W;
        const int nw4 = (KD * NW) / 4;
        for (int q = tid; q < nw4; q += stride) {
            float4 v = w4[q];
            float r0 = fmaxf(v.x, 0.f), r1 = fmaxf(v.y, 0.f);
            float r2 = fmaxf(v.z, 0.f), r3 = fmaxf(v.w, 0.f);
            s_w += r0 * r0 + r1 * r1 + r2 * r2 + r3 * r3;
        }
    }

    float s_e = 0.0f;
    {
        const float4* e4 = (const float4*)E;
        const int ne4 = (NE * KD) / 4;
        for (int q = tid; q < ne4; q += stride) {
            float4 v = e4[q];
            float r0 = fmaxf(v.x, 0.f), r1 = fmaxf(v.y, 0.f);
            float r2 = fmaxf(v.z, 0.f), r3 = fmaxf(v.w, 0.f);
            s_e += r0 * r0 + r1 * r1 + r2 * r2 + r3 * r3;
        }
    }

    float br = block_reduce(s_r);
    __syncthreads();
    float bw = block_reduce(s_w);
    __syncthreads();
    float be = block_reduce(s_e);
    if (t == 0) {
        g_pr[b] = br;
        g_pw[b] = bw;
        g_pe[b] = be;
    }

    // ---- Completion ticket: last block composes the scalar ----
    __shared__ int amLast;
    __threadfence();
    if (t == 0) {
        int r = atomicAdd(&g_done, 1);
        amLast = (r == NBLK - 1);
    }
    __syncthreads();

    if (amLast) {
        __threadfence();   // acquire all partials
        float sr = 0.f, sw = 0.f, se = 0.f, sim = 0.f;
        for (int q = t; q < NBLK; q += NTHR) {
            sr += g_pr[q];
            sw += g_pw[q];
            se += g_pe[q];
        }
        for (int q = t; q < GG; q += NTHR) sim += g_sim[q];

        float Sr  = block_reduce(sr);   __syncthreads();
        float Sw_ = block_reduce(sw);   __syncthreads();
        float Se_ = block_reduce(se);   __syncthreads();
        float Sim = block_reduce(sim);

        if (t == 0) {
            float recon = sqrtf(Sr);
            float param = sqrtf(Sw_) + sqrtf(Se_);
            float sim_p = Sim + sqrtf(g_ent[0]) * g_ent[1];
            out[0] = recon + lamb[0] * param + sim_p;
            g_done = 0;    // reset for next graph replay
        }
    }
}

// ---------------------------------------------------------------------------
// Launch: two kernels.
// Inputs (metadata order):
//  0 actual  1 prediction  2 W  3 E  4 Sw  5 Se  6 lamb  7 row_ind
//  8 word_i_indices  9 entity_j_indices  10 sample_j_indices
// ---------------------------------------------------------------------------
extern "C" void kernel_launch(void* const* d_in, const int* in_sizes, int n_in,
                              void* d_out, int out_size) {
    const float* actual = (const float*)d_in[0];
    const float* pred   = (const float*)d_in[1];
    const float* W      = (const float*)d_in[2];
    const float* E      = (const float*)d_in[3];
    const float* Sw     = (const float*)d_in[4];
    const float* Se     = (const float*)d_in[5];
    const float* lamb   = (const float*)d_in[6];
    const int*   rowi   = (const int*)  d_in[7];
    const int*   wi     = (const int*)  d_in[8];
    const int*   ej     = (const int*)  d_in[9];
    const int*   sj     = (const int*)  d_in[10];
    float* out = (float*)d_out;

    prep_k<<<PBLK, NTHR>>>(W, E, Sw, Se, rowi, wi, ej, sj);
    main_k<<<NBLK, NTHR>>>(actual, pred, W, E, lamb, out);
}

// round 6
// speedup vs baseline: 1.1707x; 1.1707x over previous
#include <cuda_runtime.h>
#include <math.h>

// Problem constants (fixed by the dataset)
#define NE 4096
#define NW 8192
#define KD 128
#define GG 1024
#define MM 64
#define JJ 256

#define NBLK 1184   // 148 SMs * 8 blocks (main kernel)
#define NTHR 256
#define NTILES 1024 // (8192/32)*(128/32) transpose tiles

// Scratch (device globals — no runtime allocation allowed)
__device__ float g_Wt[NW * KD];   // transposed W (4 MB, L2-resident between K1/K2)
__device__ float g_pr[NBLK];
__device__ float g_pw[NBLK];
__device__ float g_pe[NBLK];
__device__ float g_sim[GG];
__device__ float g_ent[2];
__device__ int   g_done = 0;      // completion ticket (reset by last block)

__device__ __forceinline__ float block_reduce(float v) {
    __shared__ float sh[32];
    int lane = threadIdx.x & 31;
    int wid  = threadIdx.x >> 5;
    #pragma unroll
    for (int o = 16; o > 0; o >>= 1) v += __shfl_down_sync(0xffffffffu, v, o);
    __syncthreads();
    if (lane == 0) sh[wid] = v;
    __syncthreads();
    v = (threadIdx.x < (NTHR >> 5)) ? sh[threadIdx.x] : 0.0f;
    if (wid == 0) {
        #pragma unroll
        for (int o = 16; o > 0; o >>= 1) v += __shfl_down_sync(0xffffffffu, v, o);
    }
    return v;   // valid in thread 0
}

// ---------------------------------------------------------------------------
// K1: transpose W (1024 tile-blocks) + entity term (1 block). ~2.5us.
// ---------------------------------------------------------------------------
__global__ void __launch_bounds__(NTHR)
prep_k(const float* __restrict__ W,
       const float* __restrict__ E,
       const float* __restrict__ Se,
       const int*   __restrict__ rowi,
       const int*   __restrict__ ej) {
    const int b = blockIdx.x;
    const int t = threadIdx.x;

    if (b < NTILES) {
        // ---- transpose one 32x32 tile of W (KD x NW) into g_Wt (NW x KD) ----
        __shared__ float tile[32][33];
        const int tx = t & 31, ty = (t >> 5) & 7;     // 32 x 8 layout (2 passes)
        const int half = t >> 8;                      // unused for 256 thr
        (void)half;
        const int tn = (b & 255) * 32;                // n base
        const int tk = (b >> 8) * 32;                 // k base
        // 256 threads, 32x8: each thread covers 4 rows
        #pragma unroll
        for (int i = 0; i < 32; i += 8)
            tile[ty + i][tx] = W[(size_t)(tk + ty + i) * NW + (tn + tx)];
        __syncthreads();
        #pragma unroll
        for (int i = 0; i < 32; i += 8)
            g_Wt[(size_t)(tn + ty + i) * KD + (tk + tx)] = tile[tx][ty + i];
    } else {
        // ---- entity term ----
        __shared__ int ejs[JJ];
        const int row_i = rowi[0];
        if (t < JJ) ejs[t] = ej[t];
        __syncthreads();
        float s_de = 0.0f;
        for (int i = t; i < JJ * KD; i += NTHR) {
            int jj = i >> 7;
            int kk = i & (KD - 1);
            float d = E[(size_t)row_i * KD + kk] - E[(size_t)ejs[jj] * KD + kk];
            s_de += d * d;
        }
        float s_se = (t < JJ) ? Se[(size_t)row_i * NE + ejs[t]] : 0.0f;
        float de = block_reduce(s_de);
        __syncthreads();
        float se = block_reduce(s_se);
        if (t == 0) { g_ent[0] = de; g_ent[1] = se; }
    }
}

// ---------------------------------------------------------------------------
// K2: gather (blocks < GG) -> streaming reduce (all) -> ticket compose.
// __launch_bounds__(256, 8) pins the hot loop at 32 regs / 8 blocks/SM.
// ---------------------------------------------------------------------------
__global__ void __launch_bounds__(NTHR, 8)
main_k(const float* __restrict__ actual,
       const float* __restrict__ pred,
       const float* __restrict__ W,
       const float* __restrict__ E,
       const float* __restrict__ Sw,
       const float* __restrict__ lamb,
       const int*   __restrict__ wi,
       const int*   __restrict__ sj,
       float* __restrict__ out) {
    const int b = blockIdx.x;
    const int t = threadIdx.x;
    const int tid    = b * NTHR + t;
    const int stride = NBLK * NTHR;

    // ---- Phase A: word gather for group b (coalesced Wt rows, L2-hot) ----
    if (b < GG) {
        __shared__ int idxs[MM];
        const int j = sj[b];
        if (t < MM) idxs[t] = wi[b * MM + t];
        __syncthreads();

        const int k    = t & (KD - 1);
        const int half = t >> 7;               // 0/1: split m-range
        const float wjk = g_Wt[(size_t)j * KD + k];

        float acc = 0.0f;
        const int m0 = half * (MM / 2);
        #pragma unroll 8
        for (int m = m0; m < m0 + MM / 2; m++) {
            float d = wjk - g_Wt[(size_t)idxs[m] * KD + k];
            acc += d * d;
        }
        float swv = (t < MM) ? Sw[(size_t)j * NW + idxs[t]] : 0.0f;

        float d2 = block_reduce(acc);
        __syncthreads();
        float sw = block_reduce(swv);
        if (t == 0) g_sim[b] = sqrtf(d2) * sw;
    }

    // ---- Phase B: HBM streaming reduce (the proven 43us loop) ----
    const float4* a4 = (const float4*)actual;
    const float4* p4 = (const float4*)pred;
    const int n4 = (NE * NW) / 4;     // 8M

    float s0 = 0.f, s1 = 0.f, s2 = 0.f, s3 = 0.f;
    int i = tid;
    for (; i + 3 * stride < n4; i += 4 * stride) {
        float4 av0 = a4[i];
        float4 av1 = a4[i +     stride];
        float4 av2 = a4[i + 2 * stride];
        float4 av3 = a4[i + 3 * stride];
        float4 pv0 = p4[i];
        float4 pv1 = p4[i +     stride];
        float4 pv2 = p4[i + 2 * stride];
        float4 pv3 = p4[i + 3 * stride];
        float d;
        d = av0.x - pv0.x; s0 += d * d; d = av0.y - pv0.y; s0 += d * d;
        d = av0.z - pv0.z; s0 += d * d; d = av0.w - pv0.w; s0 += d * d;
        d = av1.x - pv1.x; s1 += d * d; d = av1.y - pv1.y; s1 += d * d;
        d = av1.z - pv1.z; s1 += d * d; d = av1.w - pv1.w; s1 += d * d;
        d = av2.x - pv2.x; s2 += d * d; d = av2.y - pv2.y; s2 += d * d;
        d = av2.z - pv2.z; s2 += d * d; d = av2.w - pv2.w; s2 += d * d;
        d = av3.x - pv3.x; s3 += d * d; d = av3.y - pv3.y; s3 += d * d;
        d = av3.z - pv3.z; s3 += d * d; d = av3.w - pv3.w; s3 += d * d;
    }
    for (; i < n4; i += stride) {
        float4 av = a4[i];
        float4 pv = p4[i];
        float d;
        d = av.x - pv.x; s0 += d * d; d = av.y - pv.y; s0 += d * d;
        d = av.z - pv.z; s0 += d * d; d = av.w - pv.w; s0 += d * d;
    }
    float s_r = (s0 + s1) + (s2 + s3);

    float s_w = 0.0f;
    {
        const float4* w4 = (const float4*)W;
        const int nw4 = (KD * NW) / 4;
        for (int q = tid; q < nw4; q += stride) {
            float4 v = w4[q];
            float r0 = fmaxf(v.x, 0.f), r1 = fmaxf(v.y, 0.f);
            float r2 = fmaxf(v.z, 0.f), r3 = fmaxf(v.w, 0.f);
            s_w += r0 * r0 + r1 * r1 + r2 * r2 + r3 * r3;
        }
    }

    float s_e = 0.0f;
    {
        const float4* e4 = (const float4*)E;
        const int ne4 = (NE * KD) / 4;
        for (int q = tid; q < ne4; q += stride) {
            float4 v = e4[q];
            float r0 = fmaxf(v.x, 0.f), r1 = fmaxf(v.y, 0.f);
            float r2 = fmaxf(v.z, 0.f), r3 = fmaxf(v.w, 0.f);
            s_e += r0 * r0 + r1 * r1 + r2 * r2 + r3 * r3;
        }
    }

    float br = block_reduce(s_r);
    __syncthreads();
    float bw = block_reduce(s_w);
    __syncthreads();
    float be = block_reduce(s_e);
    if (t == 0) {
        g_pr[b] = br;
        g_pw[b] = bw;
        g_pe[b] = be;
    }

    // ---- Ticket: last block composes the scalar (fixed-order, deterministic) ----
    __shared__ int amLast;
    __threadfence();
    if (t == 0) {
        int r = atomicAdd(&g_done, 1);
        amLast = (r == NBLK - 1);
    }
    __syncthreads();

    if (amLast) {
        __threadfence();   // acquire all partials
        float sr = 0.f, sw = 0.f, se = 0.f, sim = 0.f;
        for (int q = t; q < NBLK; q += NTHR) {
            sr += g_pr[q];
            sw += g_pw[q];
            se += g_pe[q];
        }
        for (int q = t; q < GG; q += NTHR) sim += g_sim[q];

        float Sr  = block_reduce(sr);   __syncthreads();
        float Sw_ = block_reduce(sw);   __syncthreads();
        float Se_ = block_reduce(se);   __syncthreads();
        float Sim = block_reduce(sim);

        if (t == 0) {
            float recon = sqrtf(Sr);
            float param = sqrtf(Sw_) + sqrtf(Se_);
            float sim_p = Sim + sqrtf(g_ent[0]) * g_ent[1];
            out[0] = recon + lamb[0] * param + sim_p;
            g_done = 0;    // reset for next graph replay
        }
    }
}

// ---------------------------------------------------------------------------
// Launch: two kernels, one stream, no events.
// Inputs (metadata order):
//  0 actual  1 prediction  2 W  3 E  4 Sw  5 Se  6 lamb  7 row_ind
//  8 word_i_indices  9 entity_j_indices  10 sample_j_indices
// ---------------------------------------------------------------------------
extern "C" void kernel_launch(void* const* d_in, const int* in_sizes, int n_in,
                              void* d_out, int out_size) {
    const float* actual = (const float*)d_in[0];
    const float* pred   = (const float*)d_in[1];
    const float* W      = (const float*)d_in[2];
    const float* E      = (const float*)d_in[3];
    const float* Sw     = (const float*)d_in[4];
    const float* Se     = (const float*)d_in[5];
    const float* lamb   = (const float*)d_in[6];
    const int*   rowi   = (const int*)  d_in[7];
    const int*   wi     = (const int*)  d_in[8];
    const int*   ej     = (const int*)  d_in[9];
    const int*   sj     = (const int*)  d_in[10];
    float* out = (float*)d_out;

    prep_k<<<NTILES + 1, NTHR>>>(W, E, Se, rowi, ej);
    main_k<<<NBLK, NTHR>>>(actual, pred, W, E, Sw, lamb, wi, sj, out);
}

// round 7
// speedup vs baseline: 1.3333x; 1.1389x over previous
#include <cuda_runtime.h>
#include <math.h>

// Problem constants (fixed by the dataset)
#define NE 4096
#define NW 8192
#define KD 128
#define GG 1024
#define MM 64
#define JJ 256

#define NBLK 1184   // 148 SMs * 8 blocks (streaming kernel)
#define NTHR 256
#define NTILES 1024 // (8192/32)*(128/32) transpose tiles == GG

// Scratch (device globals — no runtime allocation allowed)
__device__ float g_Wt[NW * KD];   // transposed W (4 MB)
__device__ float g_pr[NBLK];
__device__ float g_pw[NBLK];
__device__ float g_pe[NBLK];
__device__ float g_sim[GG];
__device__ float g_ent[2];
__device__ int   g_tbar = 0;      // transpose-done counter (reset by K2 compose)
__device__ int   g_done = 0;      // K2 completion ticket  (reset by K2 compose)

__device__ __forceinline__ float block_reduce(float v) {
    __shared__ float sh[32];
    int lane = threadIdx.x & 31;
    int wid  = threadIdx.x >> 5;
    #pragma unroll
    for (int o = 16; o > 0; o >>= 1) v += __shfl_down_sync(0xffffffffu, v, o);
    __syncthreads();
    if (lane == 0) sh[wid] = v;
    __syncthreads();
    v = (threadIdx.x < (NTHR >> 5)) ? sh[threadIdx.x] : 0.0f;
    if (wid == 0) {
        #pragma unroll
        for (int o = 16; o > 0; o >>= 1) v += __shfl_down_sync(0xffffffffu, v, o);
    }
    return v;   // valid in thread 0
}

// ---------------------------------------------------------------------------
// K1: transpose -> (grid spin barrier) -> gather, + entity block.
// 1025 blocks @ 256 thr, 32 regs -> all co-resident (capacity 1184): spin safe.
// ---------------------------------------------------------------------------
__global__ void __launch_bounds__(NTHR)
prep_k(const float* __restrict__ W,
       const float* __restrict__ E,
       const float* __restrict__ Sw,
       const float* __restrict__ Se,
       const int*   __restrict__ rowi,
       const int*   __restrict__ wi,
       const int*   __restrict__ ej,
       const int*   __restrict__ sj) {
    const int b = blockIdx.x;
    const int t = threadIdx.x;

    if (b < NTILES) {
        // ---- transpose one 32x32 tile of W (KD x NW) into g_Wt (NW x KD) ----
        __shared__ float tile[32][33];
        const int tx = t & 31, ty = (t >> 5);     // 32 x 8
        const int tn = (b & 255) * 32;            // n base
        const int tk = (b >> 8) * 32;             // k base
        #pragma unroll
        for (int i = 0; i < 32; i += 8)
            tile[ty + i][tx] = W[(size_t)(tk + ty + i) * NW + (tn + tx)];
        __syncthreads();
        #pragma unroll
        for (int i = 0; i < 32; i += 8)
            g_Wt[(size_t)(tn + ty + i) * KD + (tk + tx)] = tile[tx][ty + i];

        // ---- signal + wait for all tiles (all blocks co-resident) ----
        __threadfence();
        if (t == 0) {
            atomicAdd(&g_tbar, 1);
            while (*(volatile int*)&g_tbar < NTILES) { }
        }
        __syncthreads();
        __threadfence();   // acquire g_Wt

        // ---- gather for group g = b (Wt rows are L2-hot right now) ----
        __shared__ int idxs[MM];
        const int j = sj[b];
        if (t < MM) idxs[t] = wi[b * MM + t];
        __syncthreads();

        const int k    = t & (KD - 1);
        const int half = t >> 7;              // 0/1 split of m-range
        const float wjk = g_Wt[(size_t)j * KD + k];

        float acc = 0.0f;
        const int m0 = half * (MM / 2);
        #pragma unroll 8
        for (int m = m0; m < m0 + MM / 2; m++) {
            float d = wjk - g_Wt[(size_t)idxs[m] * KD + k];
            acc += d * d;
        }
        float swv = (t < MM) ? Sw[(size_t)j * NW + idxs[t]] : 0.0f;

        float d2 = block_reduce(acc);
        __syncthreads();
        float sw = block_reduce(swv);
        if (t == 0) g_sim[b] = sqrtf(d2) * sw;
    } else {
        // ---- entity term (independent of transpose) ----
        __shared__ int ejs[JJ];
        const int row_i = rowi[0];
        if (t < JJ) ejs[t] = ej[t];
        __syncthreads();
        float s_de = 0.0f;
        for (int i = t; i < JJ * KD; i += NTHR) {
            int jj = i >> 7;
            int kk = i & (KD - 1);
            float d = E[(size_t)row_i * KD + kk] - E[(size_t)ejs[jj] * KD + kk];
            s_de += d * d;
        }
        float s_se = (t < JJ) ? Se[(size_t)row_i * NE + ejs[t]] : 0.0f;
        float de = block_reduce(s_de);
        __syncthreads();
        float se = block_reduce(s_se);
        if (t == 0) { g_ent[0] = de; g_ent[1] = se; }
    }
}

// ---------------------------------------------------------------------------
// K2: pure HBM streaming reduce (evict-first loads) + ticket compose.
// No pre-phase of any kind — the R4/R5/R6 lesson.
// ---------------------------------------------------------------------------
__global__ void __launch_bounds__(NTHR, 8)
main_k(const float* __restrict__ actual,
       const float* __restrict__ pred,
       const float* __restrict__ W,
       const float* __restrict__ E,
       const float* __restrict__ lamb,
       float* __restrict__ out) {
    const int b = blockIdx.x;
    const int t = threadIdx.x;
    const int tid    = b * NTHR + t;
    const int stride = NBLK * NTHR;

    const float4* a4 = (const float4*)actual;
    const float4* p4 = (const float4*)pred;
    const int n4 = (NE * NW) / 4;     // 8M

    float s0 = 0.f, s1 = 0.f, s2 = 0.f, s3 = 0.f;
    int i = tid;
    for (; i + 3 * stride < n4; i += 4 * stride) {
        float4 av0 = __ldcs(&a4[i]);
        float4 av1 = __ldcs(&a4[i +     stride]);
        float4 av2 = __ldcs(&a4[i + 2 * stride]);
        float4 av3 = __ldcs(&a4[i + 3 * stride]);
        float4 pv0 = __ldcs(&p4[i]);
        float4 pv1 = __ldcs(&p4[i +     stride]);
        float4 pv2 = __ldcs(&p4[i + 2 * stride]);
        float4 pv3 = __ldcs(&p4[i + 3 * stride]);
        float d;
        d = av0.x - pv0.x; s0 += d * d; d = av0.y - pv0.y; s0 += d * d;
        d = av0.z - pv0.z; s0 += d * d; d = av0.w - pv0.w; s0 += d * d;
        d = av1.x - pv1.x; s1 += d * d; d = av1.y - pv1.y; s1 += d * d;
        d = av1.z - pv1.z; s1 += d * d; d = av1.w - pv1.w; s1 += d * d;
        d = av2.x - pv2.x; s2 += d * d; d = av2.y - pv2.y; s2 += d * d;
        d = av2.z - pv2.z; s2 += d * d; d = av2.w - pv2.w; s2 += d * d;
        d = av3.x - pv3.x; s3 += d * d; d = av3.y - pv3.y; s3 += d * d;
        d = av3.z - pv3.z; s3 += d * d; d = av3.w - pv3.w; s3 += d * d;
    }
    for (; i < n4; i += stride) {
        float4 av = __ldcs(&a4[i]);
        float4 pv = __ldcs(&p4[i]);
        float d;
        d = av.x - pv.x; s0 += d * d; d = av.y - pv.y; s0 += d * d;
        d = av.z - pv.z; s0 += d * d; d = av.w - pv.w; s0 += d * d;
    }
    float s_r = (s0 + s1) + (s2 + s3);

    float s_w = 0.0f;
    {
        const float4* w4 = (const float4*)W;
        const int nw4 = (KD * NW) / 4;
        for (int q = tid; q < nw4; q += stride) {
            float4 v = __ldcs(&w4[q]);
            float r0 = fmaxf(v.x, 0.f), r1 = fmaxf(v.y, 0.f);
            float r2 = fmaxf(v.z, 0.f), r3 = fmaxf(v.w, 0.f);
            s_w += r0 * r0 + r1 * r1 + r2 * r2 + r3 * r3;
        }
    }

    float s_e = 0.0f;
    {
        const float4* e4 = (const float4*)E;
        const int ne4 = (NE * KD) / 4;
        for (int q = tid; q < ne4; q += stride) {
            float4 v = __ldcs(&e4[q]);
            float r0 = fmaxf(v.x, 0.f), r1 = fmaxf(v.y, 0.f);
            float r2 = fmaxf(v.z, 0.f), r3 = fmaxf(v.w, 0.f);
            s_e += r0 * r0 + r1 * r1 + r2 * r2 + r3 * r3;
        }
    }

    float br = block_reduce(s_r);
    __syncthreads();
    float bw = block_reduce(s_w);
    __syncthreads();
    float be = block_reduce(s_e);
    if (t == 0) {
        g_pr[b] = br;
        g_pw[b] = bw;
        g_pe[b] = be;
    }

    // ---- Ticket: last block composes (fixed-order, deterministic) ----
    __shared__ int amLast;
    __threadfence();
    if (t == 0) {
        int r = atomicAdd(&g_done, 1);
        amLast = (r == NBLK - 1);
    }
    __syncthreads();

    if (amLast) {
        __threadfence();   // acquire all partials
        float sr = 0.f, sw = 0.f, se = 0.f, sim = 0.f;
        for (int q = t; q < NBLK; q += NTHR) {
            sr += g_pr[q];
            sw += g_pw[q];
            se += g_pe[q];
        }
        for (int q = t; q < GG; q += NTHR) sim += g_sim[q];

        float Sr  = block_reduce(sr);   __syncthreads();
        float Sw_ = block_reduce(sw);   __syncthreads();
        float Se_ = block_reduce(se);   __syncthreads();
        float Sim = block_reduce(sim);

        if (t == 0) {
            float recon = sqrtf(Sr);
            float param = sqrtf(Sw_) + sqrtf(Se_);
            float sim_p = Sim + sqrtf(g_ent[0]) * g_ent[1];
            out[0] = recon + lamb[0] * param + sim_p;
            g_done = 0;    // reset for next graph replay
            g_tbar = 0;    // reset K1's barrier (K2 strictly follows K1)
        }
    }
}

// ---------------------------------------------------------------------------
// Launch: two kernels, one stream.
// Inputs (metadata order):
//  0 actual  1 prediction  2 W  3 E  4 Sw  5 Se  6 lamb  7 row_ind
//  8 word_i_indices  9 entity_j_indices  10 sample_j_indices
// ---------------------------------------------------------------------------
extern "C" void kernel_launch(void* const* d_in, const int* in_sizes, int n_in,
                              void* d_out, int out_size) {
    const float* actual = (const float*)d_in[0];
    const float* pred   = (const float*)d_in[1];
    const float* W      = (const float*)d_in[2];
    const float* E      = (const float*)d_in[3];
    const float* Sw     = (const float*)d_in[4];
    const float* Se     = (const float*)d_in[5];
    const float* lamb   = (const float*)d_in[6];
    const int*   rowi   = (const int*)  d_in[7];
    const int*   wi     = (const int*)  d_in[8];
    const int*   ej     = (const int*)  d_in[9];
    const int*   sj     = (const int*)  d_in[10];
    float* out = (float*)d_out;

    prep_k<<<NTILES + 1, NTHR>>>(W, E, Sw, Se, rowi, wi, ej, sj);
    main_k<<<NBLK, NTHR>>>(actual, pred, W, E, lamb, out);
}